// round 11
// baseline (speedup 1.0000x reference)
#include <cuda_runtime.h>
#include <cstdint>
#include <math.h>

#define BB 16
#define TT 500
#define CC 2048
#define SN 64
#define SD 512
#define CLU 8                      // CTAs per den cluster
#define CPC (SD / CLU)             // 64 columns per den CTA
#define NCLUST (BB / 2)            // 8 den clusters, 2 batches each

typedef unsigned long long ull;

__device__ float g_llh[2 * BB];    // [0..15] den, [16..31] num
__device__ int g_done;             // producer completion counter (self-resetting)

__device__ __forceinline__ float warp_max(float v) {
#pragma unroll
    for (int o = 16; o > 0; o >>= 1) v = fmaxf(v, __shfl_xor_sync(0xffffffffu, v, o));
    return v;
}
__device__ __forceinline__ float warp_sum(float v) {
#pragma unroll
    for (int o = 16; o > 0; o >>= 1) v += __shfl_xor_sync(0xffffffffu, v, o);
    return v;
}
__device__ __forceinline__ float clip30(float v) {
    return fminf(fmaxf(v, -30.f), 30.f);
}
__device__ __forceinline__ uint32_t smem_u32(const void* p) {
    uint32_t a;
    asm("{ .reg .u64 t; cvta.to.shared.u64 t, %1; cvt.u32.u64 %0, t; }" : "=r"(a) : "l"(p));
    return a;
}
__device__ __forceinline__ void st_cluster_f32(uint32_t local_addr, int rank, float v) {
    uint32_t rem;
    asm volatile("mapa.shared::cluster.u32 %0, %1, %2;" : "=r"(rem) : "r"(local_addr), "r"(rank));
    asm volatile("st.shared::cluster.f32 [%0], %1;" :: "r"(rem), "f"(v) : "memory");
}
__device__ __forceinline__ void st_cluster_u64(uint32_t local_addr, int rank, ull v) {
    uint32_t rem;
    asm volatile("mapa.shared::cluster.u32 %0, %1, %2;" : "=r"(rem) : "r"(local_addr), "r"(rank));
    asm volatile("st.shared::cluster.u64 [%0], %1;" :: "r"(rem), "l"(v) : "memory");
}
__device__ __forceinline__ void cluster_sync_() {
    asm volatile("barrier.cluster.arrive.aligned;" ::: "memory");
    asm volatile("barrier.cluster.wait.aligned;" ::: "memory");
}
__device__ __forceinline__ uint32_t ctarank_() {
    uint32_t r;
    asm("mov.u32 %0, %%cluster_ctarank;" : "=r"(r));
    return r;
}
// packed dual-fp32 fma: d = a * b + d
__device__ __forceinline__ void fma2(ull& d, ull a, ull b) {
    asm("fma.rn.f32x2 %0, %1, %2, %0;" : "+l"(d) : "l"(a), "l"(b));
}

// ---------------------------------------------------------------------------
// Denominator: 8 clusters x 8 CTAs; each cluster advances TWO batches per
// iteration (P slice in registers is batch-independent -> reused).
// Producers: warps 0-1 own batch A, warps 2-3 own batch B (parallel finalize).
// One __syncthreads + one cluster.sync per iteration = per 2 batch-steps.
// ---------------------------------------------------------------------------
__device__ void den_path2(const float* __restrict__ x, const int* __restrict__ seqlens,
                          const float* __restrict__ logA, const float* __restrict__ ls,
                          const float* __restrict__ lf, const int* __restrict__ ids_g) {
    __shared__ __align__(16) ull u2A[2][SD], u2B[2][SD];   // packed {w,w}
    __shared__ __align__(16) ull red2A[16 * 32], red2B[16 * 32];
    __shared__ float mA[2][16], mB[2][16];
    __shared__ float wrA[16], wrB[16];

    const int tid  = threadIdx.x;
    const int lane = tid & 31;
    const int rg   = tid >> 5;          // matvec row group 0..15 (32 rows each)
    const int cp   = tid & 31;          // matvec column pair 0..31
    const int r    = (int)ctarank_();
    const int cid  = blockIdx.x / CLU;  // cluster id 0..7
    const int b0   = 2 * cid, b1 = 2 * cid + 1;
    const int j0   = r * CPC + 2 * cp;
    const int L0   = seqlens[b0], L1 = seqlens[b1];
    const int Lmax = (L0 > L1) ? L0 : L1;
    const float* xb0 = x + (size_t)b0 * TT * CC;
    const float* xb1 = x + (size_t)b1 * TT * CC;

    // P slice in registers, packed per column pair (shared by both batches)
    ull pr[32];
#pragma unroll
    for (int k = 0; k < 32; ++k) {
        float2 p2;
        p2.x = __expf(logA[(size_t)(rg * 32 + k) * SD + j0]);
        p2.y = __expf(logA[(size_t)(rg * 32 + k) * SD + j0 + 1]);
        pr[k] = *(ull*)&p2;
    }

    // Producer setup: warps 0-1 -> batch A, warps 2-3 -> batch B.
    const bool isProd = (tid < 128);
    const bool isA    = (tid < 64);
    const int  c      = tid & 63;       // producer column
    const int  jcol   = r * CPC + c;
    const int  pw     = (tid >> 5) & 1; // producer warp within its group
    int myid = 0, Lme = 0;
    float emn = 0.f, logC = 0.f;
    const float* xme = isA ? xb0 : xb1;

    if (isProd) {
        Lme  = isA ? L0 : L1;
        myid = ids_g[jcol];
        float w0 = __expf(ls[jcol] + clip30(xme[myid]));
        float2 ww0 = make_float2(w0, w0);
        ull wp0 = *(ull*)&ww0;
        uint32_t ubase = smem_u32(isA ? &u2A[0][jcol] : &u2B[0][jcol]);
        uint32_t mbase = smem_u32(isA ? &mA[0][r * 2 + pw] : &mB[0][r * 2 + pw]);
#pragma unroll
        for (int q = 0; q < CLU; ++q) st_cluster_u64(ubase, q, wp0);
        float wm = warp_max(w0);
        if (lane == 0) {
#pragma unroll
            for (int q = 0; q < CLU; ++q) st_cluster_f32(mbase, q, wm);
        }
        emn = (Lme > 1) ? xme[CC + myid] : 0.f;
    }
    cluster_sync_();

    int p = 0;
    for (int t = 1; t < Lmax; ++t) {
        // matvec A then B: 32 rows x 2 cols each, packed f32x2
        ull accA = 0ull, accB = 0ull;
        {
            const ulonglong2* ua = (const ulonglong2*)&u2A[p][rg * 32];
            const ulonglong2* ub = (const ulonglong2*)&u2B[p][rg * 32];
#pragma unroll
            for (int k2 = 0; k2 < 16; ++k2) {
                ulonglong2 a2 = ua[k2];
                ulonglong2 b2 = ub[k2];
                fma2(accA, a2.x, pr[2 * k2]);
                fma2(accB, b2.x, pr[2 * k2]);
                fma2(accA, a2.y, pr[2 * k2 + 1]);
                fma2(accB, b2.y, pr[2 * k2 + 1]);
            }
        }
        red2A[rg * 32 + cp] = accA;
        red2B[rg * 32 + cp] = accB;

        // producer prep (overlapped with other warps' matvec tail)
        float E = 0.f, sc = 0.f, m = 0.f;
        bool active = false;
        if (isProd) {
            active = (t < Lme);
            E = __expf(clip30(emn));
            if (t + 1 < Lme) emn = xme[(size_t)(t + 1) * CC + myid];
            const float* marr = isA ? mA[p] : mB[p];
            m = marr[0];
#pragma unroll
            for (int i = 1; i < 16; ++i) m = fmaxf(m, marr[i]);
            sc = __fdividef(1.0f, m);
        }
        __syncthreads();

        if (isProd) {
            const float* rf = (const float*)(isA ? red2A : red2B);
            float v0 = 0.f, v1 = 0.f, v2 = 0.f, v3 = 0.f;
#pragma unroll
            for (int g2 = 0; g2 < 4; ++g2) {
                v0 += rf[(4 * g2 + 0) * 64 + c];
                v1 += rf[(4 * g2 + 1) * 64 + c];
                v2 += rf[(4 * g2 + 2) * 64 + c];
                v3 += rf[(4 * g2 + 3) * 64 + c];
            }
            float w;
            if (active) {
                w = (((v0 + v1) + (v2 + v3)) * sc) * E;
            } else {
                // frozen: forward the unchanged state into the next buffer
                w = __uint_as_float((uint32_t)(isA ? u2A[p][jcol] : u2B[p][jcol]));
            }
            float2 ww = make_float2(w, w);
            ull wp2 = *(ull*)&ww;
            uint32_t ubase = smem_u32(isA ? &u2A[1 - p][jcol] : &u2B[1 - p][jcol]);
            uint32_t mbase = smem_u32(isA ? &mA[1 - p][r * 2 + pw] : &mB[1 - p][r * 2 + pw]);
#pragma unroll
            for (int q = 0; q < CLU; ++q) st_cluster_u64(ubase, q, wp2);
            float wm = warp_max(w);
            if (lane == 0) {
#pragma unroll
                for (int q = 0; q < CLU; ++q) st_cluster_f32(mbase, q, wm);
            }
            if ((tid == 0 || tid == 64) && active) logC += __logf(m);
        }
        cluster_sync_();
        p ^= 1;
    }

    // llh = logC + log(sum_j w[j] * exp(lf[j]));  rank 0 has full state
    if (r == 0) {
        float elf = __expf(lf[tid]);
        float eA = __uint_as_float((uint32_t)u2A[p][tid]) * elf;
        float eB = __uint_as_float((uint32_t)u2B[p][tid]) * elf;
        float sA = warp_sum(eA);
        float sB = warp_sum(eB);
        if (lane == 0) { wrA[tid >> 5] = sA; wrB[tid >> 5] = sB; }
        __syncthreads();
        if (tid == 0) {
            float s = 0.f;
            for (int i = 0; i < 16; ++i) s += wrA[i];
            g_llh[b0] = logC + __logf(s);
            __threadfence();
            atomicAdd(&g_done, 1);
        }
        if (tid == 64) {
            float s = 0.f;
            for (int i = 0; i < 16; ++i) s += wrB[i];
            g_llh[b1] = logC + __logf(s);
            __threadfence();
            atomicAdd(&g_done, 1);
        }
    }
    cluster_sync_();   // no CTA exits while peers may still receive DSMEM traffic
}

// ---------------------------------------------------------------------------
// Numerator: per-batch FSM (S=64), linear state, one CTA per batch (hidden).
// ---------------------------------------------------------------------------
__device__ void num_path(int b, const float* __restrict__ x,
                         const int* __restrict__ seqlens,
                         const float* __restrict__ logA,
                         const float* __restrict__ ls,
                         const float* __restrict__ lf,
                         const int* __restrict__ ids_g) {
    __shared__ __align__(16) float Pn[SN * SN];
    __shared__ float w_n[SN];
    __shared__ float redn[8][SN];
    __shared__ float wred[2];

    const int tid = threadIdx.x;
    const int lane = tid & 31;
    const int g = tid >> 6;              // row group 0..7 (8 rows each)
    const int col = tid & 63;
    const int L = seqlens[b];
    const float* xb = x + (size_t)b * TT * CC;

    for (int i = tid; i < SN * SN; i += 512)
        Pn[i] = __expf(logA[(size_t)b * SN * SN + i]);

    int myid = 0;
    float emn = 0.f, logC = 0.f;
    if (tid < SN) {
        myid = ids_g[b * SN + tid];
        float w0 = __expf(ls[b * SN + tid] + clip30(xb[myid]));
        w_n[tid] = w0;
        float wm = warp_max(w0);
        if (lane == 0) wred[tid >> 5] = wm;
        emn = (L > 1) ? xb[CC + myid] : 0.f;
    }
    __syncthreads();

    for (int t = 1; t < L; ++t) {
        float m = fmaxf(wred[0], wred[1]);
        float E = 0.f, sc = 0.f;
        if (tid < SN) {
            sc = __fdividef(1.0f, m);
            E = __expf(clip30(emn));
            if (t + 1 < L) emn = xb[(size_t)(t + 1) * CC + myid];
        }
        float acc = 0.f;
#pragma unroll
        for (int k = 0; k < 8; ++k)
            acc = fmaf(w_n[g * 8 + k], Pn[(g * 8 + k) * SN + col], acc);
        redn[g][col] = acc;
        __syncthreads();
        if (tid < SN) {
            float v = 0.f;
#pragma unroll
            for (int g2 = 0; g2 < 8; ++g2) v += redn[g2][tid];
            float w = (v * sc) * E;
            w_n[tid] = w;
            float wm = warp_max(w);
            if (lane == 0) wred[tid >> 5] = wm;
            if (tid == 0) logC += __logf(m);
        }
        __syncthreads();
    }

    if (tid < SN) {
        float e = w_n[tid] * __expf(lf[b * SN + tid]);
        float ws = warp_sum(e);
        if (lane == 0) wred[tid >> 5] = ws;
    }
    __syncthreads();
    if (tid == 0) {
        g_llh[BB + b] = logC + __logf(wred[0] + wred[1]);
        __threadfence();
        atomicAdd(&g_done, 1);
    }
}

// Grid: 64 den CTAs (8 clusters x 8) + 16 num CTAs = 80.
// Last num CTA finalizes the output (spin on producer counter) -> ONE launch.
__global__ void __launch_bounds__(512, 1) __cluster_dims__(CLU, 1, 1)
fused_kernel(const float* __restrict__ x, const int* __restrict__ seqlens,
             const float* __restrict__ num_logA, const float* __restrict__ num_ls,
             const float* __restrict__ num_lf, const int* __restrict__ num_ids,
             const float* __restrict__ den_logA, const float* __restrict__ den_ls,
             const float* __restrict__ den_lf, const int* __restrict__ den_ids,
             float* __restrict__ out) {
    if (blockIdx.x < NCLUST * CLU) {
        den_path2(x, seqlens, den_logA, den_ls, den_lf, den_ids);
    } else {
        num_path(blockIdx.x - NCLUST * CLU, x, seqlens, num_logA, num_ls, num_lf, num_ids);
        if (blockIdx.x == NCLUST * CLU + BB - 1 && threadIdx.x == 0) {
            while (atomicAdd(&g_done, 0) < 2 * BB) {}
            __threadfence();
            float sden = 0.f, snum = 0.f;
            for (int i = 0; i < BB; ++i) {
                sden += g_llh[i];
                snum += g_llh[BB + i];
            }
            out[0] = -(snum - sden);
            atomicSub(&g_done, 2 * BB);   // reset for next graph replay
        }
    }
}

extern "C" void kernel_launch(void* const* d_in, const int* in_sizes, int n_in,
                              void* d_out, int out_size) {
    const float* x        = (const float*)d_in[0];
    const int*   seqlens  = (const int*)d_in[1];
    const float* num_logA = (const float*)d_in[2];
    const float* num_ls   = (const float*)d_in[3];
    const float* num_lf   = (const float*)d_in[4];
    const int*   num_ids  = (const int*)d_in[5];
    const float* den_logA = (const float*)d_in[6];
    const float* den_ls   = (const float*)d_in[7];
    const float* den_lf   = (const float*)d_in[8];
    const int*   den_ids  = (const int*)d_in[9];

    fused_kernel<<<NCLUST * CLU + BB, 512>>>(x, seqlens, num_logA, num_ls, num_lf,
                                             num_ids, den_logA, den_ls, den_lf,
                                             den_ids, (float*)d_out);
}

// round 12
// speedup vs baseline: 1.0852x; 1.0852x over previous
#include <cuda_runtime.h>
#include <cstdint>
#include <math.h>

#define BB 16
#define TT 500
#define CC 2048
#define SN 64
#define SD 512
#define CLU 8                      // CTAs per den cluster
#define CPC (SD / CLU)             // 64 columns per den CTA

typedef unsigned long long ull;

__device__ float g_llh[2 * BB];    // [0..15] den, [16..31] num
__device__ int g_done;             // producer completion counter (self-resetting)

__device__ __forceinline__ float warp_max(float v) {
#pragma unroll
    for (int o = 16; o > 0; o >>= 1) v = fmaxf(v, __shfl_xor_sync(0xffffffffu, v, o));
    return v;
}
__device__ __forceinline__ float warp_sum(float v) {
#pragma unroll
    for (int o = 16; o > 0; o >>= 1) v += __shfl_xor_sync(0xffffffffu, v, o);
    return v;
}
__device__ __forceinline__ float clip30(float v) {
    return fminf(fmaxf(v, -30.f), 30.f);
}
__device__ __forceinline__ uint32_t smem_u32(const void* p) {
    uint32_t a;
    asm("{ .reg .u64 t; cvta.to.shared.u64 t, %1; cvt.u32.u64 %0, t; }" : "=r"(a) : "l"(p));
    return a;
}
// inline mapa + remote store (proven pattern)
__device__ __forceinline__ void st_cluster_f32(uint32_t local_addr, int rank, float v) {
    uint32_t rem;
    asm volatile("mapa.shared::cluster.u32 %0, %1, %2;" : "=r"(rem) : "r"(local_addr), "r"(rank));
    asm volatile("st.shared::cluster.f32 [%0], %1;" :: "r"(rem), "f"(v) : "memory");
}
__device__ __forceinline__ void st_cluster_u64(uint32_t local_addr, int rank, ull v) {
    uint32_t rem;
    asm volatile("mapa.shared::cluster.u32 %0, %1, %2;" : "=r"(rem) : "r"(local_addr), "r"(rank));
    asm volatile("st.shared::cluster.u64 [%0], %1;" :: "r"(rem), "l"(v) : "memory");
}
__device__ __forceinline__ void cluster_sync_() {
    asm volatile("barrier.cluster.arrive.aligned;" ::: "memory");
    asm volatile("barrier.cluster.wait.aligned;" ::: "memory");
}
__device__ __forceinline__ uint32_t ctarank_() {
    uint32_t r;
    asm("mov.u32 %0, %%cluster_ctarank;" : "=r"(r));
    return r;
}
// packed dual-fp32 fma: d = a * b + d
__device__ __forceinline__ void fma2(ull& d, ull a, ull b) {
    asm("fma.rn.f32x2 %0, %1, %2, %0;" : "+l"(d) : "l"(a), "l"(b));
}

// ---------------------------------------------------------------------------
// Denominator: one 8-CTA cluster per batch, linear state, output-side norm.
// Per step, 3 phases:
//  1) matvec (all 512) + producer prep (E, lagged max; 64 threads)   -> bar
//  2) 64 producers: reduce partials, w -> wtmp[64] (local only)      -> bar
//  3) ALL 512 push: thread (q,col) sends ONE {w,w} u64 to rank q;
//     each warp sends one warp-max to its (q,half) slot              -> cluster.sync
// This parallelizes remote-store issue across 16 warps (R10 serialized it
// on 2 warps) without redundant MUFU/LDS (R9's mistake).
// ---------------------------------------------------------------------------
__device__ void den_path(const float* __restrict__ x, const int* __restrict__ seqlens,
                         const float* __restrict__ logA, const float* __restrict__ ls,
                         const float* __restrict__ lf, const int* __restrict__ ids_g) {
    __shared__ __align__(16) ull u2buf[2][SD];       // packed {w,w}, double-buffered
    __shared__ __align__(16) ull red2[16 * 32];      // [rg][cp] -> cols {2cp,2cp+1}
    __shared__ float m_arr[2][16];                   // [src CTA r][col half]
    __shared__ float wtmp[64];                       // finalized w, this CTA's slice
    __shared__ float warp_red[16];

    const int tid  = threadIdx.x;
    const int lane = tid & 31, wid = tid >> 5;
    const int rg   = tid >> 5;          // matvec row group 0..15 (32 rows each)
    const int cp   = tid & 31;          // matvec column pair 0..31
    const int col  = tid & 63;          // push phase: local column
    const int q    = tid >> 6;          // push phase: destination rank
    const int half = (tid >> 5) & 1;    // which 32-col half of the slice
    const int r    = (int)ctarank_();
    const int b    = blockIdx.x / CLU;
    const int j0   = r * CPC + 2 * cp;
    const int L    = seqlens[b];
    const float* xb = x + (size_t)b * TT * CC;

    // P slice in registers, packed per column pair
    ull pr[32];
#pragma unroll
    for (int k = 0; k < 32; ++k) {
        float2 p2;
        p2.x = __expf(logA[(size_t)(rg * 32 + k) * SD + j0]);
        p2.y = __expf(logA[(size_t)(rg * 32 + k) * SD + j0 + 1]);
        pr[k] = *(ull*)&p2;
    }

    // t = 0 init: all 512 threads push (1 store each), producers own em stream
    const int jcol = r * CPC + col;
    int myid = 0;
    float emn = 0.f, logC = 0.f;
    {
        int id0 = ids_g[jcol];
        float w0 = __expf(ls[jcol] + clip30(xb[id0]));
        float2 ww0 = make_float2(w0, w0);
        st_cluster_u64(smem_u32(&u2buf[0][jcol]), q, *(ull*)&ww0);
        float wm = warp_max(w0);
        if (lane == 0)
            st_cluster_f32(smem_u32(&m_arr[0][r * 2 + half]), q, wm);
        if (tid < 64) {
            myid = id0;
            emn = (L > 1) ? xb[CC + myid] : 0.f;
        }
    }
    cluster_sync_();

    int p = 0;
    for (int t = 1; t < L; ++t) {
        // phase 1: matvec partial, 32 rows x 2 cols, packed f32x2
        ull acc = 0ull;
        const ulonglong2* uu = (const ulonglong2*)&u2buf[p][rg * 32];
#pragma unroll
        for (int k2 = 0; k2 < 16; ++k2) {
            ulonglong2 u = uu[k2];
            fma2(acc, u.x, pr[2 * k2]);
            fma2(acc, u.y, pr[2 * k2 + 1]);
        }
        red2[rg * 32 + cp] = acc;
        // producer prep (64 threads), overlapped with matvec tail
        float E = 0.f, sc = 0.f, m = 0.f;
        if (tid < 64) {
            E = __expf(clip30(emn));
            if (t + 1 < L) emn = xb[(size_t)(t + 1) * CC + myid];
            m = m_arr[p][0];
#pragma unroll
            for (int i = 1; i < 16; ++i) m = fmaxf(m, m_arr[p][i]);
            sc = __fdividef(1.0f, m);
        }
        __syncthreads();

        // phase 2: producers reduce + finalize locally (no remote stores)
        if (tid < 64) {
            const float* rf = (const float*)red2;
            float v0 = 0.f, v1 = 0.f, v2 = 0.f, v3 = 0.f;
#pragma unroll
            for (int g2 = 0; g2 < 4; ++g2) {
                v0 += rf[(4 * g2 + 0) * 64 + tid];
                v1 += rf[(4 * g2 + 1) * 64 + tid];
                v2 += rf[(4 * g2 + 2) * 64 + tid];
                v3 += rf[(4 * g2 + 3) * 64 + tid];
            }
            wtmp[tid] = (((v0 + v1) + (v2 + v3)) * sc) * E;   // bounded in fp32
            if (tid == 0) logC += __logf(m);
        }
        __syncthreads();

        // phase 3: all 512 threads push one value each
        {
            float w = wtmp[col];
            float2 ww = make_float2(w, w);
            st_cluster_u64(smem_u32(&u2buf[1 - p][jcol]), q, *(ull*)&ww);
            float wm = warp_max(w);
            if (lane == 0)
                st_cluster_f32(smem_u32(&m_arr[1 - p][r * 2 + half]), q, wm);
        }
        cluster_sync_();
        p ^= 1;
    }

    // llh = logC + log(sum_j w[j] * exp(lf[j]));  rank 0 has full w
    if (r == 0) {
        float w = __uint_as_float((uint32_t)u2buf[p][tid]);   // low half
        float e = w * __expf(lf[tid]);
        float ws = warp_sum(e);
        if (lane == 0) warp_red[wid] = ws;
        __syncthreads();
        if (tid == 0) {
            float s = 0.f;
            for (int i = 0; i < 16; ++i) s += warp_red[i];
            g_llh[b] = logC + __logf(s);
            __threadfence();
            atomicAdd(&g_done, 1);
        }
    }
    cluster_sync_();   // no CTA exits while peers may still receive DSMEM traffic
}

// ---------------------------------------------------------------------------
// Numerator: per-batch FSM (S=64), linear state, one CTA per batch (hidden).
// ---------------------------------------------------------------------------
__device__ void num_path(int b, const float* __restrict__ x,
                         const int* __restrict__ seqlens,
                         const float* __restrict__ logA,
                         const float* __restrict__ ls,
                         const float* __restrict__ lf,
                         const int* __restrict__ ids_g) {
    __shared__ __align__(16) float Pn[SN * SN];
    __shared__ float w_n[SN];
    __shared__ float redn[8][SN];
    __shared__ float wred[2];

    const int tid = threadIdx.x;
    const int lane = tid & 31;
    const int g = tid >> 6;              // row group 0..7 (8 rows each)
    const int col = tid & 63;
    const int L = seqlens[b];
    const float* xb = x + (size_t)b * TT * CC;

    for (int i = tid; i < SN * SN; i += 512)
        Pn[i] = __expf(logA[(size_t)b * SN * SN + i]);

    int myid = 0;
    float emn = 0.f, logC = 0.f;
    if (tid < SN) {
        myid = ids_g[b * SN + tid];
        float w0 = __expf(ls[b * SN + tid] + clip30(xb[myid]));
        w_n[tid] = w0;
        float wm = warp_max(w0);
        if (lane == 0) wred[tid >> 5] = wm;
        emn = (L > 1) ? xb[CC + myid] : 0.f;
    }
    __syncthreads();

    for (int t = 1; t < L; ++t) {
        float m = fmaxf(wred[0], wred[1]);
        float E = 0.f, sc = 0.f;
        if (tid < SN) {
            sc = __fdividef(1.0f, m);
            E = __expf(clip30(emn));
            if (t + 1 < L) emn = xb[(size_t)(t + 1) * CC + myid];
        }
        float acc = 0.f;
#pragma unroll
        for (int k = 0; k < 8; ++k)
            acc = fmaf(w_n[g * 8 + k], Pn[(g * 8 + k) * SN + col], acc);
        redn[g][col] = acc;
        __syncthreads();
        if (tid < SN) {
            float v = 0.f;
#pragma unroll
            for (int g2 = 0; g2 < 8; ++g2) v += redn[g2][tid];
            float w = (v * sc) * E;
            w_n[tid] = w;
            float wm = warp_max(w);
            if (lane == 0) wred[tid >> 5] = wm;
            if (tid == 0) logC += __logf(m);
        }
        __syncthreads();
    }

    if (tid < SN) {
        float e = w_n[tid] * __expf(lf[b * SN + tid]);
        float ws = warp_sum(e);
        if (lane == 0) wred[tid >> 5] = ws;
    }
    __syncthreads();
    if (tid == 0) {
        g_llh[BB + b] = logC + __logf(wred[0] + wred[1]);
        __threadfence();
        atomicAdd(&g_done, 1);
    }
}

// Fused: clusters 0..15 (CTAs 0..127) = den; CTAs 128..143 = num batches 0..15.
// Last num CTA finalizes the output (spin on producer counter) -> ONE launch.
__global__ void __launch_bounds__(512, 1) __cluster_dims__(CLU, 1, 1)
fused_kernel(const float* __restrict__ x, const int* __restrict__ seqlens,
             const float* __restrict__ num_logA, const float* __restrict__ num_ls,
             const float* __restrict__ num_lf, const int* __restrict__ num_ids,
             const float* __restrict__ den_logA, const float* __restrict__ den_ls,
             const float* __restrict__ den_lf, const int* __restrict__ den_ids,
             float* __restrict__ out) {
    if (blockIdx.x < BB * CLU) {
        den_path(x, seqlens, den_logA, den_ls, den_lf, den_ids);
    } else {
        num_path(blockIdx.x - BB * CLU, x, seqlens, num_logA, num_ls, num_lf, num_ids);
        if (blockIdx.x == BB * CLU + BB - 1 && threadIdx.x == 0) {
            while (atomicAdd(&g_done, 0) < 2 * BB) {}
            __threadfence();
            float sden = 0.f, snum = 0.f;
            for (int i = 0; i < BB; ++i) {
                sden += g_llh[i];
                snum += g_llh[BB + i];
            }
            out[0] = -(snum - sden);
            atomicSub(&g_done, 2 * BB);   // reset for next graph replay
        }
    }
}

extern "C" void kernel_launch(void* const* d_in, const int* in_sizes, int n_in,
                              void* d_out, int out_size) {
    const float* x        = (const float*)d_in[0];
    const int*   seqlens  = (const int*)d_in[1];
    const float* num_logA = (const float*)d_in[2];
    const float* num_ls   = (const float*)d_in[3];
    const float* num_lf   = (const float*)d_in[4];
    const int*   num_ids  = (const int*)d_in[5];
    const float* den_logA = (const float*)d_in[6];
    const float* den_ls   = (const float*)d_in[7];
    const float* den_lf   = (const float*)d_in[8];
    const int*   den_ids  = (const int*)d_in[9];

    fused_kernel<<<BB * CLU + BB, 512>>>(x, seqlens, num_logA, num_ls, num_lf,
                                         num_ids, den_logA, den_ls, den_lf,
                                         den_ids, (float*)d_out);
}

// round 13
// speedup vs baseline: 1.4847x; 1.3681x over previous
#include <cuda_runtime.h>
#include <cstdint>
#include <math.h>

#define BB 16
#define TT 500
#define CC 2048
#define SN 64
#define SD 512
#define CLU 8                      // CTAs per den cluster
#define CPC (SD / CLU)             // 64 columns per den CTA
// per-phase incoming bytes per CTA: 8 src x (64 w-values x 8B + 2 maxima x 4B)
#define TXB (CLU * (CPC * 8 + 2 * 4))

typedef unsigned long long ull;

__device__ float g_llh[2 * BB];    // [0..15] den, [16..31] num
__device__ int g_done;             // producer completion counter (self-resetting)

__device__ __forceinline__ float warp_max(float v) {
#pragma unroll
    for (int o = 16; o > 0; o >>= 1) v = fmaxf(v, __shfl_xor_sync(0xffffffffu, v, o));
    return v;
}
__device__ __forceinline__ float warp_sum(float v) {
#pragma unroll
    for (int o = 16; o > 0; o >>= 1) v += __shfl_xor_sync(0xffffffffu, v, o);
    return v;
}
__device__ __forceinline__ float clip30(float v) {
    return fminf(fmaxf(v, -30.f), 30.f);
}
__device__ __forceinline__ uint32_t smem_u32(const void* p) {
    uint32_t a;
    asm("{ .reg .u64 t; cvta.to.shared.u64 t, %1; cvt.u32.u64 %0, t; }" : "=r"(a) : "l"(p));
    return a;
}
// async remote store with transaction count on the DESTINATION CTA's mbarrier
__device__ __forceinline__ void st_async_b64(uint32_t daddr, uint32_t mbaddr, int rank, ull v) {
    uint32_t rd, rm;
    asm volatile("mapa.shared::cluster.u32 %0, %1, %2;" : "=r"(rd) : "r"(daddr), "r"(rank));
    asm volatile("mapa.shared::cluster.u32 %0, %1, %2;" : "=r"(rm) : "r"(mbaddr), "r"(rank));
    asm volatile("st.async.shared::cluster.mbarrier::complete_tx::bytes.b64 [%0], %1, [%2];"
                 :: "r"(rd), "l"(v), "r"(rm) : "memory");
}
__device__ __forceinline__ void st_async_b32(uint32_t daddr, uint32_t mbaddr, int rank, float v) {
    uint32_t rd, rm;
    asm volatile("mapa.shared::cluster.u32 %0, %1, %2;" : "=r"(rd) : "r"(daddr), "r"(rank));
    asm volatile("mapa.shared::cluster.u32 %0, %1, %2;" : "=r"(rm) : "r"(mbaddr), "r"(rank));
    asm volatile("st.async.shared::cluster.mbarrier::complete_tx::bytes.b32 [%0], %1, [%2];"
                 :: "r"(rd), "r"(__float_as_uint(v)), "r"(rm) : "memory");
}
__device__ __forceinline__ void mbar_init(uint32_t addr, uint32_t cnt) {
    asm volatile("mbarrier.init.shared.b64 [%0], %1;" :: "r"(addr), "r"(cnt) : "memory");
}
__device__ __forceinline__ void mbar_expect_tx(uint32_t addr, uint32_t bytes) {
    asm volatile("mbarrier.arrive.expect_tx.shared.b64 _, [%0], %1;"
                 :: "r"(addr), "r"(bytes) : "memory");
}
__device__ __forceinline__ void mbar_wait_parity(uint32_t mbar, uint32_t parity) {
    asm volatile(
        "{\n\t"
        ".reg .pred P1;\n\t"
        "WAIT_LOOP_%=:\n\t"
        "mbarrier.try_wait.parity.acquire.cluster.shared::cta.b64 P1, [%0], %1, 0x989680;\n\t"
        "@P1 bra.uni WAIT_DONE_%=;\n\t"
        "bra.uni WAIT_LOOP_%=;\n\t"
        "WAIT_DONE_%=:\n\t"
        "}"
        :: "r"(mbar), "r"(parity) : "memory");
}
__device__ __forceinline__ void cluster_sync_() {
    asm volatile("barrier.cluster.arrive.aligned;" ::: "memory");
    asm volatile("barrier.cluster.wait.aligned;" ::: "memory");
}
__device__ __forceinline__ uint32_t ctarank_() {
    uint32_t r;
    asm("mov.u32 %0, %%cluster_ctarank;" : "=r"(r));
    return r;
}
// packed dual-fp32 fma: d = a * b + d
__device__ __forceinline__ void fma2(ull& d, ull a, ull b) {
    asm("fma.rn.f32x2 %0, %1, %2, %0;" : "+l"(d) : "l"(a), "l"(b));
}

// ---------------------------------------------------------------------------
// Denominator: one 8-CTA cluster per batch, linear state, output-side norm.
// NO cluster.sync in the loop: producers push {w,w} + warp maxima via st.async
// with complete_tx on the destination's mbarrier; each CTA arms its own
// mbarrier with expect_tx=TXB per phase; consumers wake on one try_wait.
// Double-buffered (u2buf/mbar[2]); parity = per-buffer use count & 1.
// ---------------------------------------------------------------------------
__device__ void den_path(const float* __restrict__ x, const int* __restrict__ seqlens,
                         const float* __restrict__ logA, const float* __restrict__ ls,
                         const float* __restrict__ lf, const int* __restrict__ ids_g) {
    __shared__ __align__(16) ull u2buf[2][SD];       // packed {w,w}, double-buffered
    __shared__ __align__(16) ull red2[16 * 32];      // [rg][cp] -> cols {2cp,2cp+1}
    __shared__ float m_arr[2][16];                   // [src CTA r][producer warp]
    __shared__ __align__(8) ull mbar[2];             // data-ready barriers (tx-based)
    __shared__ float warp_red[16];

    const int tid  = threadIdx.x;
    const int lane = tid & 31, wid = tid >> 5;
    const int rg   = tid >> 5;          // matvec row group 0..15 (32 rows each)
    const int cp   = tid & 31;          // matvec column pair 0..31
    const int r    = (int)ctarank_();
    const int b    = blockIdx.x / CLU;
    const int j0   = r * CPC + 2 * cp;
    const int L    = seqlens[b];
    const float* xb = x + (size_t)b * TT * CC;

    // P slice in registers, packed per column pair
    ull pr[32];
#pragma unroll
    for (int k = 0; k < 32; ++k) {
        float2 p2;
        p2.x = __expf(logA[(size_t)(rg * 32 + k) * SD + j0]);
        p2.y = __expf(logA[(size_t)(rg * 32 + k) * SD + j0 + 1]);
        pr[k] = *(ull*)&p2;
    }

    // init + arm both barriers BEFORE any cluster traffic
    if (tid == 0) {
        mbar_init(smem_u32(&mbar[0]), 1);   // 1 arrival per phase (the arm itself)
        mbar_init(smem_u32(&mbar[1]), 1);
        mbar_expect_tx(smem_u32(&mbar[0]), TXB);
        mbar_expect_tx(smem_u32(&mbar[1]), TXB);
    }
    __syncthreads();
    cluster_sync_();    // all inits/arms visible cluster-wide before any st.async

    // t = 0 init (threads 0..63 own this CTA's 64 columns)
    int myid = 0;
    float emn = 0.f, logC = 0.f;
    const int jcol = r * CPC + tid;     // valid when tid < 64
    if (tid < 64) {
        myid = ids_g[jcol];
        float w0 = __expf(ls[jcol] + clip30(xb[myid]));
        float2 ww0 = make_float2(w0, w0);
        ull wp0 = *(ull*)&ww0;
#pragma unroll
        for (int q = 0; q < CLU; ++q)
            st_async_b64(smem_u32(&u2buf[0][jcol]), smem_u32(&mbar[0]), q, wp0);
        float wm = warp_max(w0);
        if (lane == 0) {
#pragma unroll
            for (int q = 0; q < CLU; ++q)
                st_async_b32(smem_u32(&m_arr[0][r * 2 + wid]), smem_u32(&mbar[0]), q, wm);
        }
        emn = (L > 1) ? xb[CC + myid] : 0.f;
    }

    int p = 0;
    unsigned uc0 = 0, uc1 = 0;          // per-buffer use counters -> phase parity
    for (int t = 1; t < L; ++t) {
        unsigned par = p ? (uc1++ & 1u) : (uc0++ & 1u);
        mbar_wait_parity(smem_u32(&mbar[p]), par);
        // re-arm this buffer's barrier for its NEXT fill (consumed at t+2)
        if (tid == 0) mbar_expect_tx(smem_u32(&mbar[p]), TXB);

        // matvec partial: 32 rows x 2 cols, packed f32x2, direct on u2buf[p]
        ull acc = 0ull;
        const ulonglong2* uu = (const ulonglong2*)&u2buf[p][rg * 32];
#pragma unroll
        for (int k2 = 0; k2 < 16; ++k2) {
            ulonglong2 u = uu[k2];
            fma2(acc, u.x, pr[2 * k2]);
            fma2(acc, u.y, pr[2 * k2 + 1]);
        }
        red2[rg * 32 + cp] = acc;
        // producer prep (64 threads), overlapped with matvec tail
        float E = 0.f, sc = 0.f, m = 0.f;
        if (tid < 64) {
            E = __expf(clip30(emn));
            if (t + 1 < L) emn = xb[(size_t)(t + 1) * CC + myid];
            m = m_arr[p][0];
#pragma unroll
            for (int i = 1; i < 16; ++i) m = fmaxf(m, m_arr[p][i]);
            sc = __fdividef(1.0f, m);
        }
        __syncthreads();

        if (tid < 64) {
            // reduce 16 partials for my col (4-way trees)
            const float* rf = (const float*)red2;
            float v0 = 0.f, v1 = 0.f, v2 = 0.f, v3 = 0.f;
#pragma unroll
            for (int g2 = 0; g2 < 4; ++g2) {
                v0 += rf[(4 * g2 + 0) * 64 + tid];
                v1 += rf[(4 * g2 + 1) * 64 + tid];
                v2 += rf[(4 * g2 + 2) * 64 + tid];
                v3 += rf[(4 * g2 + 3) * 64 + tid];
            }
            float w = (((v0 + v1) + (v2 + v3)) * sc) * E;   // bounded in fp32
            float2 ww = make_float2(w, w);
            ull wp2 = *(ull*)&ww;
#pragma unroll
            for (int q = 0; q < CLU; ++q)
                st_async_b64(smem_u32(&u2buf[1 - p][jcol]), smem_u32(&mbar[1 - p]), q, wp2);
            float wm = warp_max(w);
            if (lane == 0) {
#pragma unroll
                for (int q = 0; q < CLU; ++q)
                    st_async_b32(smem_u32(&m_arr[1 - p][r * 2 + wid]), smem_u32(&mbar[1 - p]), q, wm);
            }
            if (tid == 0) logC += __logf(m);
        }
        p ^= 1;
    }

    // final wait: ALL CTAs prove the last pushes landed (also exit safety)
    {
        unsigned par = p ? (uc1++ & 1u) : (uc0++ & 1u);
        mbar_wait_parity(smem_u32(&mbar[p]), par);
    }

    // llh = logC + log(sum_j w[j] * exp(lf[j]));  rank 0 has full w
    if (r == 0) {
        float w = __uint_as_float((uint32_t)u2buf[p][tid]);   // low half
        float e = w * __expf(lf[tid]);
        float ws = warp_sum(e);
        if (lane == 0) warp_red[wid] = ws;
        __syncthreads();
        if (tid == 0) {
            float s = 0.f;
            for (int i = 0; i < 16; ++i) s += warp_red[i];
            g_llh[b] = logC + __logf(s);
            __threadfence();
            atomicAdd(&g_done, 1);
        }
    }
    cluster_sync_();   // no CTA exits while peers may still receive traffic
}

// ---------------------------------------------------------------------------
// Numerator: per-batch FSM (S=64), linear state, one CTA per batch (hidden).
// ---------------------------------------------------------------------------
__device__ void num_path(int b, const float* __restrict__ x,
                         const int* __restrict__ seqlens,
                         const float* __restrict__ logA,
                         const float* __restrict__ ls,
                         const float* __restrict__ lf,
                         const int* __restrict__ ids_g) {
    __shared__ __align__(16) float Pn[SN * SN];
    __shared__ float w_n[SN];
    __shared__ float redn[8][SN];
    __shared__ float wred[2];

    const int tid = threadIdx.x;
    const int lane = tid & 31;
    const int g = tid >> 6;              // row group 0..7 (8 rows each)
    const int col = tid & 63;
    const int L = seqlens[b];
    const float* xb = x + (size_t)b * TT * CC;

    for (int i = tid; i < SN * SN; i += 512)
        Pn[i] = __expf(logA[(size_t)b * SN * SN + i]);

    int myid = 0;
    float emn = 0.f, logC = 0.f;
    if (tid < SN) {
        myid = ids_g[b * SN + tid];
        float w0 = __expf(ls[b * SN + tid] + clip30(xb[myid]));
        w_n[tid] = w0;
        float wm = warp_max(w0);
        if (lane == 0) wred[tid >> 5] = wm;
        emn = (L > 1) ? xb[CC + myid] : 0.f;
    }
    __syncthreads();

    for (int t = 1; t < L; ++t) {
        float m = fmaxf(wred[0], wred[1]);
        float E = 0.f, sc = 0.f;
        if (tid < SN) {
            sc = __fdividef(1.0f, m);
            E = __expf(clip30(emn));
            if (t + 1 < L) emn = xb[(size_t)(t + 1) * CC + myid];
        }
        float acc = 0.f;
#pragma unroll
        for (int k = 0; k < 8; ++k)
            acc = fmaf(w_n[g * 8 + k], Pn[(g * 8 + k) * SN + col], acc);
        redn[g][col] = acc;
        __syncthreads();
        if (tid < SN) {
            float v = 0.f;
#pragma unroll
            for (int g2 = 0; g2 < 8; ++g2) v += redn[g2][tid];
            float w = (v * sc) * E;
            w_n[tid] = w;
            float wm = warp_max(w);
            if (lane == 0) wred[tid >> 5] = wm;
            if (tid == 0) logC += __logf(m);
        }
        __syncthreads();
    }

    if (tid < SN) {
        float e = w_n[tid] * __expf(lf[b * SN + tid]);
        float ws = warp_sum(e);
        if (lane == 0) wred[tid >> 5] = ws;
    }
    __syncthreads();
    if (tid == 0) {
        g_llh[BB + b] = logC + __logf(wred[0] + wred[1]);
        __threadfence();
        atomicAdd(&g_done, 1);
    }
}

// Fused: clusters 0..15 (CTAs 0..127) = den; CTAs 128..143 = num batches 0..15.
// Last num CTA finalizes the output (spin on producer counter) -> ONE launch.
__global__ void __launch_bounds__(512, 1) __cluster_dims__(CLU, 1, 1)
fused_kernel(const float* __restrict__ x, const int* __restrict__ seqlens,
             const float* __restrict__ num_logA, const float* __restrict__ num_ls,
             const float* __restrict__ num_lf, const int* __restrict__ num_ids,
             const float* __restrict__ den_logA, const float* __restrict__ den_ls,
             const float* __restrict__ den_lf, const int* __restrict__ den_ids,
             float* __restrict__ out) {
    if (blockIdx.x < BB * CLU) {
        den_path(x, seqlens, den_logA, den_ls, den_lf, den_ids);
    } else {
        num_path(blockIdx.x - BB * CLU, x, seqlens, num_logA, num_ls, num_lf, num_ids);
        if (blockIdx.x == BB * CLU + BB - 1 && threadIdx.x == 0) {
            while (atomicAdd(&g_done, 0) < 2 * BB) {}
            __threadfence();
            float sden = 0.f, snum = 0.f;
            for (int i = 0; i < BB; ++i) {
                sden += g_llh[i];
                snum += g_llh[BB + i];
            }
            out[0] = -(snum - sden);
            atomicSub(&g_done, 2 * BB);   // reset for next graph replay
        }
    }
}

extern "C" void kernel_launch(void* const* d_in, const int* in_sizes, int n_in,
                              void* d_out, int out_size) {
    const float* x        = (const float*)d_in[0];
    const int*   seqlens  = (const int*)d_in[1];
    const float* num_logA = (const float*)d_in[2];
    const float* num_ls   = (const float*)d_in[3];
    const float* num_lf   = (const float*)d_in[4];
    const int*   num_ids  = (const int*)d_in[5];
    const float* den_logA = (const float*)d_in[6];
    const float* den_ls   = (const float*)d_in[7];
    const float* den_lf   = (const float*)d_in[8];
    const int*   den_ids  = (const int*)d_in[9];

    fused_kernel<<<BB * CLU + BB, 512>>>(x, seqlens, num_logA, num_ls, num_lf,
                                         num_ids, den_logA, den_ls, den_lf,
                                         den_ids, (float*)d_out);
}

// round 14
// speedup vs baseline: 1.5518x; 1.0452x over previous
#include <cuda_runtime.h>
#include <cstdint>
#include <math.h>

#define BB 16
#define TT 500
#define CC 2048
#define SN 64
#define SD 512
#define CLU 8                      // CTAs per den cluster
#define CPC (SD / CLU)             // 64 columns per den CTA
#define TXW (CLU * CPC * 8)        // per-phase w bytes per CTA: 8 src x 64 x 8B
#define TXM (CLU * 2 * 4)          // per-phase m bytes per CTA: 8 src x 2 x 4B

typedef unsigned long long ull;

__device__ float g_llh[2 * BB];    // [0..15] den, [16..31] num
__device__ int g_done;             // producer completion counter (self-resetting)

__device__ __forceinline__ float warp_max(float v) {
#pragma unroll
    for (int o = 16; o > 0; o >>= 1) v = fmaxf(v, __shfl_xor_sync(0xffffffffu, v, o));
    return v;
}
__device__ __forceinline__ float warp_sum(float v) {
#pragma unroll
    for (int o = 16; o > 0; o >>= 1) v += __shfl_xor_sync(0xffffffffu, v, o);
    return v;
}
__device__ __forceinline__ float clip30(float v) {
    return fminf(fmaxf(v, -30.f), 30.f);
}
__device__ __forceinline__ uint32_t smem_u32(const void* p) {
    uint32_t a;
    asm("{ .reg .u64 t; cvta.to.shared.u64 t, %1; cvt.u32.u64 %0, t; }" : "=r"(a) : "l"(p));
    return a;
}
// async remote store with transaction count on the DESTINATION CTA's mbarrier
__device__ __forceinline__ void st_async_b64(uint32_t daddr, uint32_t mbaddr, int rank, ull v) {
    uint32_t rd, rm;
    asm volatile("mapa.shared::cluster.u32 %0, %1, %2;" : "=r"(rd) : "r"(daddr), "r"(rank));
    asm volatile("mapa.shared::cluster.u32 %0, %1, %2;" : "=r"(rm) : "r"(mbaddr), "r"(rank));
    asm volatile("st.async.shared::cluster.mbarrier::complete_tx::bytes.b64 [%0], %1, [%2];"
                 :: "r"(rd), "l"(v), "r"(rm) : "memory");
}
__device__ __forceinline__ void st_async_b32(uint32_t daddr, uint32_t mbaddr, int rank, float v) {
    uint32_t rd, rm;
    asm volatile("mapa.shared::cluster.u32 %0, %1, %2;" : "=r"(rd) : "r"(daddr), "r"(rank));
    asm volatile("mapa.shared::cluster.u32 %0, %1, %2;" : "=r"(rm) : "r"(mbaddr), "r"(rank));
    asm volatile("st.async.shared::cluster.mbarrier::complete_tx::bytes.b32 [%0], %1, [%2];"
                 :: "r"(rd), "r"(__float_as_uint(v)), "r"(rm) : "memory");
}
__device__ __forceinline__ void mbar_init(uint32_t addr, uint32_t cnt) {
    asm volatile("mbarrier.init.shared.b64 [%0], %1;" :: "r"(addr), "r"(cnt) : "memory");
}
__device__ __forceinline__ void mbar_expect_tx(uint32_t addr, uint32_t bytes) {
    asm volatile("mbarrier.arrive.expect_tx.shared.b64 _, [%0], %1;"
                 :: "r"(addr), "r"(bytes) : "memory");
}
__device__ __forceinline__ void mbar_wait_parity(uint32_t mbar, uint32_t parity) {
    asm volatile(
        "{\n\t"
        ".reg .pred P1;\n\t"
        "WAIT_LOOP_%=:\n\t"
        "mbarrier.try_wait.parity.acquire.cluster.shared::cta.b64 P1, [%0], %1, 0x989680;\n\t"
        "@P1 bra.uni WAIT_DONE_%=;\n\t"
        "bra.uni WAIT_LOOP_%=;\n\t"
        "WAIT_DONE_%=:\n\t"
        "}"
        :: "r"(mbar), "r"(parity) : "memory");
}
__device__ __forceinline__ void cluster_sync_() {
    asm volatile("barrier.cluster.arrive.aligned;" ::: "memory");
    asm volatile("barrier.cluster.wait.aligned;" ::: "memory");
}
__device__ __forceinline__ uint32_t ctarank_() {
    uint32_t r;
    asm("mov.u32 %0, %%cluster_ctarank;" : "=r"(r));
    return r;
}
// packed dual-fp32 fma: d = a * b + d
__device__ __forceinline__ void fma2(ull& d, ull a, ull b) {
    asm("fma.rn.f32x2 %0, %1, %2, %0;" : "+l"(d) : "l"(a), "l"(b));
}

// ---------------------------------------------------------------------------
// Denominator: one 8-CTA cluster per batch, linear state, output-side norm.
// SPLIT barriers: mbarW (w payload, 4096B) gates the matvec; mbarM (maxima,
// 64B) is waited only by producers AFTER their matvec share (slack; the m
// push trails the w push by ~150cyc and is now off the critical path).
// ---------------------------------------------------------------------------
__device__ void den_path(const float* __restrict__ x, const int* __restrict__ seqlens,
                         const float* __restrict__ logA, const float* __restrict__ ls,
                         const float* __restrict__ lf, const int* __restrict__ ids_g) {
    __shared__ __align__(16) ull u2buf[2][SD];       // packed {w,w}, double-buffered
    __shared__ __align__(16) ull red2[16 * 32];      // [rg][cp] -> cols {2cp,2cp+1}
    __shared__ float m_arr[2][16];                   // [src CTA r][producer warp]
    __shared__ __align__(8) ull mbarW[2], mbarM[2];  // split data-ready barriers
    __shared__ float warp_red[16];

    const int tid  = threadIdx.x;
    const int lane = tid & 31, wid = tid >> 5;
    const int rg   = tid >> 5;          // matvec row group 0..15 (32 rows each)
    const int cp   = tid & 31;          // matvec column pair 0..31
    const int r    = (int)ctarank_();
    const int b    = blockIdx.x / CLU;
    const int j0   = r * CPC + 2 * cp;
    const int L    = seqlens[b];
    const float* xb = x + (size_t)b * TT * CC;

    // P slice in registers, packed per column pair
    ull pr[32];
#pragma unroll
    for (int k = 0; k < 32; ++k) {
        float2 p2;
        p2.x = __expf(logA[(size_t)(rg * 32 + k) * SD + j0]);
        p2.y = __expf(logA[(size_t)(rg * 32 + k) * SD + j0 + 1]);
        pr[k] = *(ull*)&p2;
    }

    // init + arm all barriers BEFORE any cluster traffic
    if (tid == 0) {
        mbar_init(smem_u32(&mbarW[0]), 1);
        mbar_init(smem_u32(&mbarW[1]), 1);
        mbar_init(smem_u32(&mbarM[0]), 1);
        mbar_init(smem_u32(&mbarM[1]), 1);
        mbar_expect_tx(smem_u32(&mbarW[0]), TXW);
        mbar_expect_tx(smem_u32(&mbarW[1]), TXW);
        mbar_expect_tx(smem_u32(&mbarM[0]), TXM);
        mbar_expect_tx(smem_u32(&mbarM[1]), TXM);
    }
    __syncthreads();
    cluster_sync_();    // all inits/arms visible cluster-wide before any st.async

    // t = 0 init (threads 0..63 own this CTA's 64 columns)
    int myid = 0;
    float emn = 0.f, logC = 0.f;
    const int jcol = r * CPC + tid;     // valid when tid < 64
    if (tid < 64) {
        myid = ids_g[jcol];
        float w0 = __expf(ls[jcol] + clip30(xb[myid]));
        float2 ww0 = make_float2(w0, w0);
        ull wp0 = *(ull*)&ww0;
#pragma unroll
        for (int q = 0; q < CLU; ++q)
            st_async_b64(smem_u32(&u2buf[0][jcol]), smem_u32(&mbarW[0]), q, wp0);
        float wm = warp_max(w0);
        if (lane == 0) {
#pragma unroll
            for (int q = 0; q < CLU; ++q)
                st_async_b32(smem_u32(&m_arr[0][r * 2 + wid]), smem_u32(&mbarM[0]), q, wm);
        }
        emn = (L > 1) ? xb[CC + myid] : 0.f;
    }

    int p = 0;
    unsigned uc0 = 0, uc1 = 0;          // per-buffer use counters -> phase parity
    for (int t = 1; t < L; ++t) {
        unsigned par = p ? (uc1++ & 1u) : (uc0++ & 1u);
        mbar_wait_parity(smem_u32(&mbarW[p]), par);
        // re-arm W for this buffer's NEXT fill (consumed at t+2)
        if (tid == 0) mbar_expect_tx(smem_u32(&mbarW[p]), TXW);

        // matvec partial: 32 rows x 2 cols, packed f32x2, direct on u2buf[p]
        ull acc = 0ull;
        const ulonglong2* uu = (const ulonglong2*)&u2buf[p][rg * 32];
#pragma unroll
        for (int k2 = 0; k2 < 16; ++k2) {
            ulonglong2 u = uu[k2];
            fma2(acc, u.x, pr[2 * k2]);
            fma2(acc, u.y, pr[2 * k2 + 1]);
        }
        red2[rg * 32 + cp] = acc;
        // producer prep (64 threads): wait m (long arrived; hidden in slack)
        float E = 0.f, sc = 0.f, m = 0.f;
        if (tid < 64) {
            mbar_wait_parity(smem_u32(&mbarM[p]), par);
            if (tid == 0) mbar_expect_tx(smem_u32(&mbarM[p]), TXM);
            E = __expf(clip30(emn));
            if (t + 1 < L) emn = xb[(size_t)(t + 1) * CC + myid];
            m = m_arr[p][0];
#pragma unroll
            for (int i = 1; i < 16; ++i) m = fmaxf(m, m_arr[p][i]);
            sc = __fdividef(1.0f, m);
        }
        __syncthreads();

        if (tid < 64) {
            // reduce 16 partials for my col (4-way trees)
            const float* rf = (const float*)red2;
            float v0 = 0.f, v1 = 0.f, v2 = 0.f, v3 = 0.f;
#pragma unroll
            for (int g2 = 0; g2 < 4; ++g2) {
                v0 += rf[(4 * g2 + 0) * 64 + tid];
                v1 += rf[(4 * g2 + 1) * 64 + tid];
                v2 += rf[(4 * g2 + 2) * 64 + tid];
                v3 += rf[(4 * g2 + 3) * 64 + tid];
            }
            float w = (((v0 + v1) + (v2 + v3)) * sc) * E;   // bounded in fp32
            float2 ww = make_float2(w, w);
            ull wp2 = *(ull*)&ww;
#pragma unroll
            for (int q = 0; q < CLU; ++q)
                st_async_b64(smem_u32(&u2buf[1 - p][jcol]), smem_u32(&mbarW[1 - p]), q, wp2);
            float wm = warp_max(w);
            if (lane == 0) {
#pragma unroll
                for (int q = 0; q < CLU; ++q)
                    st_async_b32(smem_u32(&m_arr[1 - p][r * 2 + wid]), smem_u32(&mbarM[1 - p]), q, wm);
            }
            if (tid == 0) logC += __logf(m);
        }
        p ^= 1;
    }

    // final waits: prove ALL in-flight pushes landed (w by everyone, m by tid0)
    {
        unsigned par = p ? (uc1++ & 1u) : (uc0++ & 1u);
        mbar_wait_parity(smem_u32(&mbarW[p]), par);
        if (tid == 0) mbar_wait_parity(smem_u32(&mbarM[p]), par);
    }

    // llh = logC + log(sum_j w[j] * exp(lf[j]));  rank 0 has full w
    if (r == 0) {
        float w = __uint_as_float((uint32_t)u2buf[p][tid]);   // low half
        float e = w * __expf(lf[tid]);
        float ws = warp_sum(e);
        if (lane == 0) warp_red[wid] = ws;
        __syncthreads();
        if (tid == 0) {
            float s = 0.f;
            for (int i = 0; i < 16; ++i) s += warp_red[i];
            g_llh[b] = logC + __logf(s);
            __threadfence();
            atomicAdd(&g_done, 1);
        }
    }
    cluster_sync_();   // no CTA exits while peers may still receive traffic
}

// ---------------------------------------------------------------------------
// Numerator: per-batch FSM (S=64), linear state, one CTA per batch (hidden).
// ---------------------------------------------------------------------------
__device__ void num_path(int b, const float* __restrict__ x,
                         const int* __restrict__ seqlens,
                         const float* __restrict__ logA,
                         const float* __restrict__ ls,
                         const float* __restrict__ lf,
                         const int* __restrict__ ids_g) {
    __shared__ __align__(16) float Pn[SN * SN];
    __shared__ float w_n[SN];
    __shared__ float redn[8][SN];
    __shared__ float wred[2];

    const int tid = threadIdx.x;
    const int lane = tid & 31;
    const int g = tid >> 6;              // row group 0..7 (8 rows each)
    const int col = tid & 63;
    const int L = seqlens[b];
    const float* xb = x + (size_t)b * TT * CC;

    for (int i = tid; i < SN * SN; i += 512)
        Pn[i] = __expf(logA[(size_t)b * SN * SN + i]);

    int myid = 0;
    float emn = 0.f, logC = 0.f;
    if (tid < SN) {
        myid = ids_g[b * SN + tid];
        float w0 = __expf(ls[b * SN + tid] + clip30(xb[myid]));
        w_n[tid] = w0;
        float wm = warp_max(w0);
        if (lane == 0) wred[tid >> 5] = wm;
        emn = (L > 1) ? xb[CC + myid] : 0.f;
    }
    __syncthreads();

    for (int t = 1; t < L; ++t) {
        float m = fmaxf(wred[0], wred[1]);
        float E = 0.f, sc = 0.f;
        if (tid < SN) {
            sc = __fdividef(1.0f, m);
            E = __expf(clip30(emn));
            if (t + 1 < L) emn = xb[(size_t)(t + 1) * CC + myid];
        }
        float acc = 0.f;
#pragma unroll
        for (int k = 0; k < 8; ++k)
            acc = fmaf(w_n[g * 8 + k], Pn[(g * 8 + k) * SN + col], acc);
        redn[g][col] = acc;
        __syncthreads();
        if (tid < SN) {
            float v = 0.f;
#pragma unroll
            for (int g2 = 0; g2 < 8; ++g2) v += redn[g2][tid];
            float w = (v * sc) * E;
            w_n[tid] = w;
            float wm = warp_max(w);
            if (lane == 0) wred[tid >> 5] = wm;
            if (tid == 0) logC += __logf(m);
        }
        __syncthreads();
    }

    if (tid < SN) {
        float e = w_n[tid] * __expf(lf[b * SN + tid]);
        float ws = warp_sum(e);
        if (lane == 0) wred[tid >> 5] = ws;
    }
    __syncthreads();
    if (tid == 0) {
        g_llh[BB + b] = logC + __logf(wred[0] + wred[1]);
        __threadfence();
        atomicAdd(&g_done, 1);
    }
}

// Fused: clusters 0..15 (CTAs 0..127) = den; CTAs 128..143 = num batches 0..15.
// Last num CTA finalizes the output (spin on producer counter) -> ONE launch.
__global__ void __launch_bounds__(512, 1) __cluster_dims__(CLU, 1, 1)
fused_kernel(const float* __restrict__ x, const int* __restrict__ seqlens,
             const float* __restrict__ num_logA, const float* __restrict__ num_ls,
             const float* __restrict__ num_lf, const int* __restrict__ num_ids,
             const float* __restrict__ den_logA, const float* __restrict__ den_ls,
             const float* __restrict__ den_lf, const int* __restrict__ den_ids,
             float* __restrict__ out) {
    if (blockIdx.x < BB * CLU) {
        den_path(x, seqlens, den_logA, den_ls, den_lf, den_ids);
    } else {
        num_path(blockIdx.x - BB * CLU, x, seqlens, num_logA, num_ls, num_lf, num_ids);
        if (blockIdx.x == BB * CLU + BB - 1 && threadIdx.x == 0) {
            while (atomicAdd(&g_done, 0) < 2 * BB) {}
            __threadfence();
            float sden = 0.f, snum = 0.f;
            for (int i = 0; i < BB; ++i) {
                sden += g_llh[i];
                snum += g_llh[BB + i];
            }
            out[0] = -(snum - sden);
            atomicSub(&g_done, 2 * BB);   // reset for next graph replay
        }
    }
}

extern "C" void kernel_launch(void* const* d_in, const int* in_sizes, int n_in,
                              void* d_out, int out_size) {
    const float* x        = (const float*)d_in[0];
    const int*   seqlens  = (const int*)d_in[1];
    const float* num_logA = (const float*)d_in[2];
    const float* num_ls   = (const float*)d_in[3];
    const float* num_lf   = (const float*)d_in[4];
    const int*   num_ids  = (const int*)d_in[5];
    const float* den_logA = (const float*)d_in[6];
    const float* den_ls   = (const float*)d_in[7];
    const float* den_lf   = (const float*)d_in[8];
    const int*   den_ids  = (const int*)d_in[9];

    fused_kernel<<<BB * CLU + BB, 512>>>(x, seqlens, num_logA, num_ls, num_lf,
                                         num_ids, den_logA, den_ls, den_lf,
                                         den_ids, (float*)d_out);
}